// round 6
// baseline (speedup 1.0000x reference)
#include <cuda_runtime.h>

// ---------------------------------------------------------------------------
// Net_VIF: 6 chained quadrilinear (4D) LUT interpolations, fully fused,
// bit-exact vs the JAX reference (sequential rn multiplies, corner fold
// c=0..15, separate rn mul / rn add).
//
// R6 = R5 (64B-block layout + quad-cooperative fetch + 4x4 register
// transpose) + occupancy push:
//  - lazy per-group weight generation w = rn(rn(p01[j]*sel2)*sel3)
//    (same rounding chain as reference, ~20 fewer live registers)
//  - 128-thread blocks, __launch_bounds__(128, 6) -> 24 warps/SM
// ---------------------------------------------------------------------------

#define D   17
#define D2  289
#define D3  4913
#define D4  83521
#define N_LUTS 6

// block layout: entry = cell*4 + (b2*2 + b3). 6 * 83521 * 4 * 16B ~= 32 MB.
__device__ __align__(128) float4 g_lutB[N_LUTS][D4 * 4];

__global__ void lut_pack_kernel(const float* __restrict__ s0, const float* __restrict__ s1,
                                const float* __restrict__ s2, const float* __restrict__ s3,
                                const float* __restrict__ s4, const float* __restrict__ s5) {
    int i = blockIdx.x * blockDim.x + threadIdx.x;
    if (i >= D4) return;
    int which = blockIdx.y;
    const float* src = (which == 0) ? s0 : (which == 1) ? s1 : (which == 2) ? s2
                     : (which == 3) ? s3 : (which == 4) ? s4 : s5;
    bool c4 = (which != 5);
    int i3 = i % D;
    int i2 = (i / D) % D;
#pragma unroll
    for (int e = 0; e < 4; ++e) {
        int b2 = e >> 1, b3 = e & 1;
        float4 v = make_float4(0.0f, 0.0f, 0.0f, 0.0f);
        if ((i2 + b2) <= D - 1 && (i3 + b3) <= D - 1) {
            int o = i + b2 * D + b3;
            v.x = src[o];
            v.y = src[D4 + o];
            v.z = src[2 * D4 + o];
            v.w = c4 ? src[3 * D4 + o] : 0.0f;
        }
        g_lutB[which][i * 4 + e] = v;
    }
}

// One butterfly step of the 4x4 cross-lane transpose on a register pair.
// h = (lane & m) != 0. Pure bit movement.
__device__ __forceinline__ void xstep(float4& lo, float4& hi, bool h, int m) {
    const unsigned FULL = 0xffffffffu;
    float sx = h ? lo.x : hi.x;
    float sy = h ? lo.y : hi.y;
    float sz = h ? lo.z : hi.z;
    float sw = h ? lo.w : hi.w;
    float rx = __shfl_xor_sync(FULL, sx, m);
    float ry = __shfl_xor_sync(FULL, sy, m);
    float rz = __shfl_xor_sync(FULL, sz, m);
    float rw = __shfl_xor_sync(FULL, sw, m);
    lo.x = h ? rx : lo.x;  hi.x = h ? hi.x : rx;
    lo.y = h ? ry : lo.y;  hi.y = h ? hi.y : ry;
    lo.z = h ? rz : lo.z;  hi.z = h ? hi.z : rz;
    lo.w = h ? rw : lo.w;  hi.w = h ? hi.w : rw;
}

// Fold one group of 4 corners (fixed (b2,b3) -> element e; j = 0..3) into acc.
// Weight chain rn(rn(p01[j]*s2)*s3) == reference ((w0*w1)*w2)*w3 exactly.
__device__ __forceinline__ void fold_group(float4& acc, const float4* vj,
                                           const float* p01, float s2, float s3) {
#pragma unroll
    for (int j = 0; j < 4; ++j) {
        float w = __fmul_rn(__fmul_rn(p01[j], s2), s3);
        acc.x = __fadd_rn(acc.x, __fmul_rn(vj[j].x, w));
        acc.y = __fadd_rn(acc.y, __fmul_rn(vj[j].y, w));
        acc.z = __fadd_rn(acc.z, __fmul_rn(vj[j].z, w));
        acc.w = __fadd_rn(acc.w, __fmul_rn(vj[j].w, w));
    }
}

__device__ __forceinline__ float4 coop_stage(const float4* __restrict__ lut,
                                             float4 x, int lane) {
    const unsigned FULL = 0xffffffffu;
    const int s  = lane & 3;
    const int qb = lane & ~3;

    // Own indices / fractions (exact ops, identical to reference).
    float t0 = __saturatef(x.x) * 16.0f;
    float t1 = __saturatef(x.y) * 16.0f;
    float t2 = __saturatef(x.z) * 16.0f;
    float t3 = __saturatef(x.w) * 16.0f;
    int i0 = min((int)t0, D - 2);
    int i1 = min((int)t1, D - 2);
    int i2 = min((int)t2, D - 2);
    int i3 = min((int)t3, D - 2);
    float f0 = t0 - (float)i0;
    float f1 = t1 - (float)i1;
    float f2 = t2 - (float)i2;
    float f3 = t3 - (float)i3;
    float g0 = 1.0f - f0, g1 = 1.0f - f1, g2 = 1.0f - f2, g3 = 1.0f - f3;
    int mybase = ((i0 * D + i1) * D + i2) * D + i3;

    // Broadcast the quad's four cell bases.
    int b0v = __shfl_sync(FULL, mybase, qb);
    int b1v = __shfl_sync(FULL, mybase, qb + 1);
    int b2v = __shfl_sync(FULL, mybase, qb + 2);
    int b3v = __shfl_sync(FULL, mybase, qb + 3);

    // 16 cooperative loads: round r serves pixel qb+r; j indexes (b0,b1);
    // lane s takes element s of the 64B block (one cache line per quad).
    float4 v[4][4];                      // v[r][j] before transpose
#pragma unroll
    for (int j = 0; j < 4; ++j) {
        const int oj = (j & 1) * D3 + ((j >> 1) & 1) * D2;   // b0*D3 + b1*D2
        v[0][j] = __ldg(lut + (b0v + oj) * 4 + s);
        v[1][j] = __ldg(lut + (b1v + oj) * 4 + s);
        v[2][j] = __ldg(lut + (b2v + oj) * 4 + s);
        v[3][j] = __ldg(lut + (b3v + oj) * 4 + s);
    }

    // 4x4 transpose across quad lanes (per j): v[e][j] = element e of OWN
    // pixel's block j, e = 2*b2 + b3.
    const bool h1 = (s & 1) != 0;
    const bool h2 = (s & 2) != 0;
#pragma unroll
    for (int j = 0; j < 4; ++j) {
        xstep(v[0][j], v[1][j], h1, 1);
        xstep(v[2][j], v[3][j], h1, 1);
        xstep(v[0][j], v[2][j], h2, 2);
        xstep(v[1][j], v[3][j], h2, 2);
    }

    // p01[j], j = b0 + 2*b1 (reference rn(w0*w1)).
    float p01[4];
    p01[0] = __fmul_rn(g0, g1);
    p01[1] = __fmul_rn(f0, g1);
    p01[2] = __fmul_rn(g0, f1);
    p01[3] = __fmul_rn(f0, f1);

    // Sequential fold c = 0..15: groups (b2,b3) = (0,0),(1,0),(0,1),(1,1)
    // -> element rows e = 0, 2, 1, 3; within each group j = 0..3.
    float4 acc = make_float4(0.0f, 0.0f, 0.0f, 0.0f);
    fold_group(acc, v[0], p01, g2, g3);   // c = 0..3
    fold_group(acc, v[2], p01, f2, g3);   // c = 4..7
    fold_group(acc, v[1], p01, g2, f3);   // c = 8..11
    fold_group(acc, v[3], p01, f2, f3);   // c = 12..15
    return acc;
}

__global__ void __launch_bounds__(128, 6)
net_vif_kernel(const float* __restrict__ vi,
               const float* __restrict__ ir,
               float* __restrict__ out) {
    const int HW = 512 * 512;                  // 1<<18
    int p  = blockIdx.x * blockDim.x + threadIdx.x;
    int hw = p & (HW - 1);
    int b  = p >> 18;
    int lane = threadIdx.x & 31;

    const float* vb = vi + (size_t)b * 3 * HW + hw;
    float4 x;
    x.x = vb[0];
    x.y = vb[HW];
    x.z = vb[2 * HW];
    x.w = ir[(size_t)b * HW + hw];

    x = coop_stage(g_lutB[0], x, lane);   // lut8
    x = coop_stage(g_lutB[1], x, lane);   // lut00
    x = coop_stage(g_lutB[2], x, lane);   // lut01
    x = coop_stage(g_lutB[3], x, lane);   // lut02
    x = coop_stage(g_lutB[4], x, lane);   // lut03
    x = coop_stage(g_lutB[5], x, lane);   // lutpgf (no final clip)

    float* ob = out + (size_t)b * 3 * HW + hw;
    ob[0]      = x.x;
    ob[HW]     = x.y;
    ob[2 * HW] = x.z;
}

extern "C" void kernel_launch(void* const* d_in, const int* in_sizes, int n_in,
                              void* d_out, int out_size) {
    const float* vi = (const float*)d_in[0];   // [8,3,512,512]
    const float* ir = (const float*)d_in[1];   // [8,1,512,512]

    dim3 pg((D4 + 255) / 256, N_LUTS);
    lut_pack_kernel<<<pg, 256>>>((const float*)d_in[2], (const float*)d_in[3],
                                 (const float*)d_in[4], (const float*)d_in[5],
                                 (const float*)d_in[6], (const float*)d_in[7]);

    const int total = 8 * 512 * 512;           // 2,097,152
    net_vif_kernel<<<total / 128, 128>>>(vi, ir, (float*)d_out);
}

// round 7
// speedup vs baseline: 1.2471x; 1.2471x over previous
#include <cuda_runtime.h>

// ---------------------------------------------------------------------------
// Net_VIF: 6 chained quadrilinear (4D) LUT interpolations, fully fused,
// bit-exact vs the JAX reference (sequential rn multiplies, corner fold
// c=0..15, separate rn mul / rn add per element).
//
// R7 = R5 (64B-block layout, quad-cooperative fetch, 4x4 register transpose,
// 256 threads x 2 CTAs/SM) + packed f32x2 fold:
//  - corners carried as 2 x u64 (xy, zw) from the LDG.128 onward
//  - fold uses mul.rn.f32x2 / add.rn.f32x2 (per-element rn == __fmul_rn /
//    __fadd_rn) -> 80 issue slots/stage instead of 128, FMA pipe halved,
//    bit-exactness untouched.
// R6's occupancy push (24 warps/SM) regressed via L1 thrash; reverted.
// ---------------------------------------------------------------------------

#define D   17
#define D2  289
#define D3  4913
#define D4  83521
#define N_LUTS 6

typedef unsigned long long u64;

// block layout: entry = cell*4 + (b2*2 + b3). 6 * 83521 * 4 * 16B ~= 32 MB.
__device__ __align__(128) float4 g_lutB[N_LUTS][D4 * 4];

__global__ void lut_pack_kernel(const float* __restrict__ s0, const float* __restrict__ s1,
                                const float* __restrict__ s2, const float* __restrict__ s3,
                                const float* __restrict__ s4, const float* __restrict__ s5) {
    int i = blockIdx.x * blockDim.x + threadIdx.x;
    if (i >= D4) return;
    int which = blockIdx.y;
    const float* src = (which == 0) ? s0 : (which == 1) ? s1 : (which == 2) ? s2
                     : (which == 3) ? s3 : (which == 4) ? s4 : s5;
    bool c4 = (which != 5);
    int i3 = i % D;
    int i2 = (i / D) % D;
#pragma unroll
    for (int e = 0; e < 4; ++e) {
        int b2 = e >> 1, b3 = e & 1;
        float4 v = make_float4(0.0f, 0.0f, 0.0f, 0.0f);
        if ((i2 + b2) <= D - 1 && (i3 + b3) <= D - 1) {
            int o = i + b2 * D + b3;
            v.x = src[o];
            v.y = src[D4 + o];
            v.z = src[2 * D4 + o];
            v.w = c4 ? src[3 * D4 + o] : 0.0f;
        }
        g_lutB[which][i * 4 + e] = v;
    }
}

// -------- packed f32x2 helpers (per-element IEEE rn, same as scalar rn) ----
__device__ __forceinline__ u64 mul2(u64 a, u64 b) {
    u64 r; asm("mul.rn.f32x2 %0, %1, %2;" : "=l"(r) : "l"(a), "l"(b)); return r;
}
__device__ __forceinline__ u64 add2(u64 a, u64 b) {
    u64 r; asm("add.rn.f32x2 %0, %1, %2;" : "=l"(r) : "l"(a), "l"(b)); return r;
}
__device__ __forceinline__ u64 packdup(float w) {
    u64 r; asm("mov.b64 %0, {%1, %2};" : "=l"(r) : "f"(w), "f"(w)); return r;
}

// corner payload: xy = channels (x,y), zw = channels (z,w)
struct C2 { u64 xy, zw; };

// One butterfly step of the 4x4 cross-lane transpose. Pure bit movement.
__device__ __forceinline__ void xstep(C2& lo, C2& hi, bool h, int m) {
    const unsigned FULL = 0xffffffffu;
    u64 s0 = h ? lo.xy : hi.xy;
    u64 s1 = h ? lo.zw : hi.zw;
    u64 r0 = __shfl_xor_sync(FULL, s0, m);
    u64 r1 = __shfl_xor_sync(FULL, s1, m);
    lo.xy = h ? r0 : lo.xy;  hi.xy = h ? hi.xy : r0;
    lo.zw = h ? r1 : lo.zw;  hi.zw = h ? hi.zw : r1;
}

__device__ __forceinline__ float4 coop_stage(const float4* __restrict__ lut,
                                             float4 x, int lane) {
    const unsigned FULL = 0xffffffffu;
    const int s  = lane & 3;
    const int qb = lane & ~3;

    // Own indices / fractions (exact ops, identical to reference).
    float t0 = __saturatef(x.x) * 16.0f;
    float t1 = __saturatef(x.y) * 16.0f;
    float t2 = __saturatef(x.z) * 16.0f;
    float t3 = __saturatef(x.w) * 16.0f;
    int i0 = min((int)t0, D - 2);
    int i1 = min((int)t1, D - 2);
    int i2 = min((int)t2, D - 2);
    int i3 = min((int)t3, D - 2);
    float f0 = t0 - (float)i0;
    float f1 = t1 - (float)i1;
    float f2 = t2 - (float)i2;
    float f3 = t3 - (float)i3;
    float g0 = 1.0f - f0, g1 = 1.0f - f1, g2 = 1.0f - f2, g3 = 1.0f - f3;
    int mybase = ((i0 * D + i1) * D + i2) * D + i3;

    // Broadcast the quad's four cell bases.
    int b0v = __shfl_sync(FULL, mybase, qb);
    int b1v = __shfl_sync(FULL, mybase, qb + 1);
    int b2v = __shfl_sync(FULL, mybase, qb + 2);
    int b3v = __shfl_sync(FULL, mybase, qb + 3);

    // 16 cooperative loads: round r serves pixel qb+r; j indexes (b0,b1);
    // lane s takes element s of the 64B block (one cache line per quad).
    C2 v[4][4];                       // v[r][j] before transpose
#pragma unroll
    for (int j = 0; j < 4; ++j) {
        const int oj = (j & 1) * D3 + ((j >> 1) & 1) * D2;   // b0*D3 + b1*D2
        const ulonglong2 a0 = __ldg((const ulonglong2*)(lut + (b0v + oj) * 4 + s));
        const ulonglong2 a1 = __ldg((const ulonglong2*)(lut + (b1v + oj) * 4 + s));
        const ulonglong2 a2 = __ldg((const ulonglong2*)(lut + (b2v + oj) * 4 + s));
        const ulonglong2 a3 = __ldg((const ulonglong2*)(lut + (b3v + oj) * 4 + s));
        v[0][j].xy = a0.x; v[0][j].zw = a0.y;
        v[1][j].xy = a1.x; v[1][j].zw = a1.y;
        v[2][j].xy = a2.x; v[2][j].zw = a2.y;
        v[3][j].xy = a3.x; v[3][j].zw = a3.y;
    }

    // 4x4 transpose across quad lanes: v[e][j] = element e (= 2*b2 + b3)
    // of OWN pixel's block j.
    const bool h1 = (s & 1) != 0;
    const bool h2 = (s & 2) != 0;
#pragma unroll
    for (int j = 0; j < 4; ++j) {
        xstep(v[0][j], v[1][j], h1, 1);
        xstep(v[2][j], v[3][j], h1, 1);
        xstep(v[0][j], v[2][j], h2, 2);
        xstep(v[1][j], v[3][j], h2, 2);
    }

    // Weights in the reference's exact rounding order:
    // w[c] = ((w0*w1)*w2)*w3, c = b0 | b1<<1 | b2<<2 | b3<<3.
    float p01[4];
    p01[0] = __fmul_rn(g0, g1);
    p01[1] = __fmul_rn(f0, g1);
    p01[2] = __fmul_rn(g0, f1);
    p01[3] = __fmul_rn(f0, f1);
    float p012[8];
#pragma unroll
    for (int j = 0; j < 4; ++j) {
        p012[j]     = __fmul_rn(p01[j], g2);
        p012[4 + j] = __fmul_rn(p01[j], f2);
    }
    float w[16];
#pragma unroll
    for (int j = 0; j < 8; ++j) {
        w[j]     = __fmul_rn(p012[j], g3);
        w[8 + j] = __fmul_rn(p012[j], f3);
    }

    // Sequential fold c = 0..15 (reference order) with packed f32x2:
    // per-element rounding identical to separate rn mul / rn add; the two
    // u64 halves are independent per-channel chains. Corner rows e for
    // groups c = 0..3 / 4..7 / 8..11 / 12..15 are e = 0, 2, 1, 3.
    u64 accxy = 0ull, acczw = 0ull;     // bits of (+0.0f, +0.0f)
    const int erow[4] = { 0, 2, 1, 3 };
#pragma unroll
    for (int g = 0; g < 4; ++g) {
#pragma unroll
        for (int j = 0; j < 4; ++j) {
            const int c = g * 4 + j;
            const u64 wp = packdup(w[c]);
            const C2 vv = v[erow[g]][j];
            accxy = add2(accxy, mul2(vv.xy, wp));
            acczw = add2(acczw, mul2(vv.zw, wp));
        }
    }

    float4 r;
    asm("mov.b64 {%0, %1}, %2;" : "=f"(r.x), "=f"(r.y) : "l"(accxy));
    asm("mov.b64 {%0, %1}, %2;" : "=f"(r.z), "=f"(r.w) : "l"(acczw));
    return r;
}

__global__ void __launch_bounds__(256, 2)
net_vif_kernel(const float* __restrict__ vi,
               const float* __restrict__ ir,
               float* __restrict__ out) {
    const int HW = 512 * 512;                  // 1<<18
    int p  = blockIdx.x * blockDim.x + threadIdx.x;
    int hw = p & (HW - 1);
    int b  = p >> 18;
    int lane = threadIdx.x & 31;

    const float* vb = vi + (size_t)b * 3 * HW + hw;
    float4 x;
    x.x = vb[0];
    x.y = vb[HW];
    x.z = vb[2 * HW];
    x.w = ir[(size_t)b * HW + hw];

    x = coop_stage(g_lutB[0], x, lane);   // lut8
    x = coop_stage(g_lutB[1], x, lane);   // lut00
    x = coop_stage(g_lutB[2], x, lane);   // lut01
    x = coop_stage(g_lutB[3], x, lane);   // lut02
    x = coop_stage(g_lutB[4], x, lane);   // lut03
    x = coop_stage(g_lutB[5], x, lane);   // lutpgf (no final clip)

    float* ob = out + (size_t)b * 3 * HW + hw;
    ob[0]      = x.x;
    ob[HW]     = x.y;
    ob[2 * HW] = x.z;
}

extern "C" void kernel_launch(void* const* d_in, const int* in_sizes, int n_in,
                              void* d_out, int out_size) {
    const float* vi = (const float*)d_in[0];   // [8,3,512,512]
    const float* ir = (const float*)d_in[1];   // [8,1,512,512]

    dim3 pg((D4 + 255) / 256, N_LUTS);
    lut_pack_kernel<<<pg, 256>>>((const float*)d_in[2], (const float*)d_in[3],
                                 (const float*)d_in[4], (const float*)d_in[5],
                                 (const float*)d_in[6], (const float*)d_in[7]);

    const int total = 8 * 512 * 512;           // 2,097,152
    net_vif_kernel<<<total / 256, 256>>>(vi, ir, (float*)d_out);
}